// round 4
// baseline (speedup 1.0000x reference)
#include <cuda_runtime.h>

#define B_TOT 8192
#define T_STEPS 128
#define P_LANES 8

// ---------------- packed f32x2 helpers ----------------
__device__ __forceinline__ unsigned long long pack2(float x, float y) {
    unsigned long long r;
    asm("mov.b64 %0, {%1, %2};" : "=l"(r) : "f"(x), "f"(y));
    return r;
}
__device__ __forceinline__ float2 unpack2(unsigned long long v) {
    float2 r;
    asm("mov.b64 {%0, %1}, %2;" : "=f"(r.x), "=f"(r.y) : "l"(v));
    return r;
}
__device__ __forceinline__ void ffma2(unsigned long long& d,
                                      unsigned long long a,
                                      unsigned long long b) {
    asm("fma.rn.f32x2 %0, %1, %2, %0;" : "+l"(d) : "l"(a), "l"(b));
}

// MUFU.TANH-based sigmoid: 1 MUFU + 2 FMA. Used for gates r/z and input
// embeddings, whose errors (~2.5e-4) are attenuated through the recurrence.
__device__ __forceinline__ float tanh_approx(float x) {
    float r;
    asm("tanh.approx.f32 %0, %1;" : "=f"(r) : "f"(x));
    return r;
}
__device__ __forceinline__ float sigmoidf(float x) {
    return fmaf(0.5f, tanh_approx(0.5f * x), 0.5f);
}
// Exact-ish tanh (2^-21) for the n gate, which writes h directly.
// MUFU is not the binding pipe, so this precision costs nothing.
__device__ __forceinline__ float tanh_exact(float x) {
    return 1.0f - __fdividef(2.0f, __expf(2.0f * x) + 1.0f);
}

// =====================================================================
// Fused kernel: per-(b,p) GRU over T=128 + lane projection + pairwise
// competition MLP. All 8 lanes of a batch element live in one block;
// pressures cross the stage boundary through shared memory.
//
// GRU gate rows: 0..9 = r, 10..19 = z, 20..29 = n
// r,z combined: grz = [Wih_rz | Whh_rz] @ [x; h] + (bih+bhh)_rz
// n split:      inn = Wih_n x + bih_n,   hn = Whh_n h + bhh_n
// Weights column-major in smem; accumulators init'd from the bias column
// (LDS.128) so no x1.0 multiply column is needed.
// =====================================================================
__global__ __launch_bounds__(256, 2) void frap_kernel(
    const float* __restrict__ feature,   // (B, 16)
    const float* __restrict__ history,   // (B, T, 24)
    const float* __restrict__ emb_phase, // (2,4)
    const float* __restrict__ w_veh,     // (1,4)
    const float* __restrict__ b_veh,     // (4)
    const float* __restrict__ w_hist,    // (3,4)
    const float* __restrict__ b_hist,    // (4)
    const float* __restrict__ wih,       // (30,4)
    const float* __restrict__ whh,       // (30,10)
    const float* __restrict__ bih,       // (30)
    const float* __restrict__ bhh,       // (30)
    const float* __restrict__ w_lane,    // (18,16)
    const float* __restrict__ b_lane,    // (16)
    const float* __restrict__ wf,        // (32,20)
    const float* __restrict__ bf,        // (20)
    const float* __restrict__ wc,        // (4,20)
    const float* __restrict__ bc,        // (20)
    const float* __restrict__ wz,        // (20,20)
    const float* __restrict__ bz,        // (20)
    const float* __restrict__ wo,        // (20,1)
    const float* __restrict__ bo,        // (1)
    const float* __restrict__ emb_const, // (2,4)
    const int*   __restrict__ relation,  // (8,7)
    const int*   __restrict__ pfl,       // (8)
    float* __restrict__ out)             // (B, 8)
{
    // --- GRU weights (col-major) ---
    __shared__ __align__(16) float wrz_s[15 * 20];  // cols: x0..3,h0..9,bias
    __shared__ __align__(16) float win_s[5 * 12];   // cols: x0..3,bias (pad 12)
    __shared__ __align__(16) float whn_s[11 * 12];  // cols: h0..9,bias (pad 12)
    __shared__ __align__(16) float wlane_s[18 * 16]; // pre-scaled by 2
    __shared__ __align__(16) float blane_s[16];      // pre-scaled by 2
    // --- pair-stage weights ---
    __shared__ __align__(16) float wf_s[32 * 20];
    __shared__ __align__(16) float wz_s[20 * 20];
    __shared__ __align__(16) float y_s[56 * 20];    // relu(const@wc+bc)
    __shared__ __align__(16) float bf_s[20];
    __shared__ __align__(16) float bz_s[20];
    __shared__ __align__(16) float wo_s[20];
    __shared__ int   pfl_s[8];
    __shared__ float bo_s;
    // --- cross-stage pressures, transposed [feature][thread] ---
    __shared__ float press_s[16][264];

    const int tid = threadIdx.x;

    for (int idx = tid; idx < 15 * 20; idx += 256) {
        int k = idx / 20, j = idx % 20;
        float v;
        if (k < 4)        v = wih[j * 4 + k];
        else if (k < 14)  v = whh[j * 10 + (k - 4)];
        else              v = bih[j] + bhh[j];
        wrz_s[idx] = v;
    }
    for (int idx = tid; idx < 5 * 12; idx += 256) {
        int k = idx / 12, i = idx % 12;
        float v = 0.0f;
        if (i < 10) v = (k < 4) ? wih[(20 + i) * 4 + k] : bih[20 + i];
        win_s[idx] = v;
    }
    for (int idx = tid; idx < 11 * 12; idx += 256) {
        int k = idx / 12, i = idx % 12;
        float v = 0.0f;
        if (i < 10) v = (k < 10) ? whh[(20 + i) * 10 + k] : bhh[20 + i];
        whn_s[idx] = v;
    }
    // pressure = 2*relu(proj) == relu(2*proj): fold the 2x into the weights
    for (int idx = tid; idx < 18 * 16; idx += 256) wlane_s[idx] = 2.0f * w_lane[idx];
    if (tid < 16) blane_s[tid] = 2.0f * b_lane[tid];

    for (int idx = tid; idx < 640; idx += 256) wf_s[idx] = wf[idx];
    for (int idx = tid; idx < 400; idx += 256) wz_s[idx] = wz[idx];
    if (tid < 20) { bf_s[tid] = bf[tid]; bz_s[tid] = bz[tid]; wo_s[tid] = wo[tid]; }
    if (tid < 8) pfl_s[tid] = pfl[tid];
    if (tid == 0) bo_s = bo[0];
    for (int idx = tid; idx < 56 * 20; idx += 256) {
        int pr = idx / 20, l = idx % 20;
        int rel = relation[pr];
        float a = bc[l];
        a = fmaf(emb_const[rel * 4 + 0], wc[0 * 20 + l], a);
        a = fmaf(emb_const[rel * 4 + 1], wc[1 * 20 + l], a);
        a = fmaf(emb_const[rel * 4 + 2], wc[2 * 20 + l], a);
        a = fmaf(emb_const[rel * 4 + 3], wc[3 * 20 + l], a);
        y_s[idx] = fmaxf(a, 0.0f);
    }
    __syncthreads();

    const int gid = blockIdx.x * 256 + tid;
    const int b = gid >> 3;
    const int p = gid & 7;

    // per-thread uniform params (broadcast loads, L1-resident)
    float wh0[4], wh1[4], wh2[4], bh[4];
#pragma unroll
    for (int k = 0; k < 4; k++) {
        wh0[k] = __ldg(&w_hist[k]);
        wh1[k] = __ldg(&w_hist[4 + k]);
        wh2[k] = __ldg(&w_hist[8 + k]);
        bh[k]  = __ldg(&b_hist[k]);
    }

    // feature scalars only — f_phase/f_veh computed after the loop (reg trim)
    const int   pbit = (int)feature[b * 16 + p];
    const float veh  = feature[b * 16 + 8 + p];

    float h[10];
#pragma unroll
    for (int i = 0; i < 10; i++) h[i] = 0.0f;

    const float* hp = history + (size_t)b * T_STEPS * 24 + p;
    float c0 = hp[0], c1 = hp[8], c2 = hp[16];

#pragma unroll 1
    for (int t = 0; t < T_STEPS; t++) {
        float n0 = 0.f, n1 = 0.f, n2 = 0.f;
        if (t + 1 < T_STEPS) {
            const float* q = hp + 24;
            n0 = q[0]; n1 = q[8]; n2 = q[16];
            hp = q;
        }

        // x_t = sigmoid(hist3 @ w_hist + b_hist)
        float x[4];
#pragma unroll
        for (int k = 0; k < 4; k++)
            x[k] = sigmoidf(fmaf(c2, wh2[k],
                            fmaf(c1, wh1[k],
                            fmaf(c0, wh0[k], bh[k]))));

        // ---- r,z combined: 20 outputs, bias-init + 14 input cols ----
        unsigned long long arz[10];
        {
            const ulonglong2* bcol = (const ulonglong2*)(wrz_s + 14 * 20);
#pragma unroll
            for (int m = 0; m < 5; m++) {
                ulonglong2 v = bcol[m];
                arz[2 * m] = v.x; arz[2 * m + 1] = v.y;
            }
        }
#pragma unroll
        for (int k = 0; k < 14; k++) {
            float v = (k < 4) ? x[k] : h[k - 4];
            unsigned long long vv = pack2(v, v);
            const ulonglong2* col = (const ulonglong2*)(wrz_s + k * 20);
#pragma unroll
            for (int m = 0; m < 5; m++) {
                ulonglong2 w = col[m];
                ffma2(arz[2 * m],     w.x, vv);
                ffma2(arz[2 * m + 1], w.y, vv);
            }
        }

        // ---- inn (bias-init + 4 x cols), hn (bias-init + 10 h cols) ----
        unsigned long long ain[6], ahn[6];
        {
            const ulonglong2* bi  = (const ulonglong2*)(win_s + 4 * 12);
            const ulonglong2* bhp = (const ulonglong2*)(whn_s + 10 * 12);
#pragma unroll
            for (int m = 0; m < 3; m++) {
                ulonglong2 v1 = bi[m];
                ain[2 * m] = v1.x; ain[2 * m + 1] = v1.y;
                ulonglong2 v2 = bhp[m];
                ahn[2 * m] = v2.x; ahn[2 * m + 1] = v2.y;
            }
        }
#pragma unroll
        for (int k = 0; k < 4; k++) {
            unsigned long long vv = pack2(x[k], x[k]);
            const ulonglong2* col = (const ulonglong2*)(win_s + k * 12);
#pragma unroll
            for (int m = 0; m < 3; m++) {
                ulonglong2 w = col[m];
                ffma2(ain[2 * m],     w.x, vv);
                ffma2(ain[2 * m + 1], w.y, vv);
            }
        }
#pragma unroll
        for (int k = 0; k < 10; k++) {
            unsigned long long vv = pack2(h[k], h[k]);
            const ulonglong2* col = (const ulonglong2*)(whn_s + k * 12);
#pragma unroll
            for (int m = 0; m < 3; m++) {
                ulonglong2 w = col[m];
                ffma2(ahn[2 * m],     w.x, vv);
                ffma2(ahn[2 * m + 1], w.y, vv);
            }
        }

        // ---- gates ----
        float r[10], z[10];
#pragma unroll
        for (int m = 0; m < 5; m++) {
            float2 ar = unpack2(arz[m]);
            r[2 * m]     = sigmoidf(ar.x);
            r[2 * m + 1] = sigmoidf(ar.y);
            float2 az = unpack2(arz[5 + m]);
            z[2 * m]     = sigmoidf(az.x);
            z[2 * m + 1] = sigmoidf(az.y);
        }
#pragma unroll
        for (int m = 0; m < 5; m++) {
            float2 gi = unpack2(ain[m]);
            float2 gh = unpack2(ahn[m]);
            float nn0 = tanh_exact(fmaf(r[2 * m],     gh.x, gi.x));
            float nn1 = tanh_exact(fmaf(r[2 * m + 1], gh.y, gi.y));
            // h' = n + z*(h - n)
            h[2 * m]     = fmaf(z[2 * m],     h[2 * m]     - nn0, nn0);
            h[2 * m + 1] = fmaf(z[2 * m + 1], h[2 * m + 1] - nn1, nn1);
        }

        c0 = n0; c1 = n1; c2 = n2;
    }

    // ---- lane projection: relu([f_veh, f_phase, h] @ (2*w_lane) + 2*b_lane) ----
    {
        float lf[18];
#pragma unroll
        for (int k = 0; k < 4; k++) {
            lf[k]     = sigmoidf(fmaf(veh, __ldg(&w_veh[k]), __ldg(&b_veh[k])));
            lf[4 + k] = sigmoidf(__ldg(&emb_phase[pbit * 4 + k]));
        }
#pragma unroll
        for (int i = 0; i < 10; i++) lf[8 + i] = h[i];

        float acc[16];
#pragma unroll
        for (int l = 0; l < 16; l++) acc[l] = blane_s[l];
#pragma unroll
        for (int m = 0; m < 18; m++) {
            float v = lf[m];
            const float4* row = (const float4*)(wlane_s + m * 16);
#pragma unroll
            for (int q = 0; q < 4; q++) {
                float4 w = row[q];
                acc[4 * q + 0] = fmaf(v, w.x, acc[4 * q + 0]);
                acc[4 * q + 1] = fmaf(v, w.y, acc[4 * q + 1]);
                acc[4 * q + 2] = fmaf(v, w.z, acc[4 * q + 2]);
                acc[4 * q + 3] = fmaf(v, w.w, acc[4 * q + 3]);
            }
        }
        // transposed store: conflict-free (lane-consecutive per feature l)
#pragma unroll
        for (int l = 0; l < 16; l++)
            press_s[l][tid] = fmaxf(acc[l], 0.0f);
    }
    __syncthreads();

    // =================== pairwise competition stage ===================
    const int i = p;
    const int rowbase = tid & 0xF8;   // this thread's batch-row base in press_s

    float pi[16];
    {
        const int ci = rowbase + pfl_s[i];
#pragma unroll
        for (int l = 0; l < 16; l++) pi[l] = press_s[l][ci];
    }

    float sum = 0.0f;
#pragma unroll 1
    for (int jx = 0; jx < 7; jx++) {
        const int j = jx + (jx >= i ? 1 : 0);
        float pj[16];
        {
            const int cj = rowbase + pfl_s[j];
#pragma unroll
            for (int l = 0; l < 16; l++) pj[l] = press_s[l][cj];
        }

        float xa[20];
        {
            const float4* bfp = (const float4*)bf_s;
#pragma unroll
            for (int q = 0; q < 5; q++) {
                float4 v = bfp[q];
                xa[4 * q + 0] = v.x; xa[4 * q + 1] = v.y;
                xa[4 * q + 2] = v.z; xa[4 * q + 3] = v.w;
            }
        }
#pragma unroll
        for (int m = 0; m < 16; m++) {
            float v = pi[m];
            const float4* row = (const float4*)(wf_s + m * 20);
#pragma unroll
            for (int q = 0; q < 5; q++) {
                float4 w = row[q];
                xa[4 * q + 0] = fmaf(v, w.x, xa[4 * q + 0]);
                xa[4 * q + 1] = fmaf(v, w.y, xa[4 * q + 1]);
                xa[4 * q + 2] = fmaf(v, w.z, xa[4 * q + 2]);
                xa[4 * q + 3] = fmaf(v, w.w, xa[4 * q + 3]);
            }
        }
#pragma unroll
        for (int m = 0; m < 16; m++) {
            float v = pj[m];
            const float4* row = (const float4*)(wf_s + (16 + m) * 20);
#pragma unroll
            for (int q = 0; q < 5; q++) {
                float4 w = row[q];
                xa[4 * q + 0] = fmaf(v, w.x, xa[4 * q + 0]);
                xa[4 * q + 1] = fmaf(v, w.y, xa[4 * q + 1]);
                xa[4 * q + 2] = fmaf(v, w.z, xa[4 * q + 2]);
                xa[4 * q + 3] = fmaf(v, w.w, xa[4 * q + 3]);
            }
        }

        // xa = relu(xa) * y[i][jx]
        const float4* yrow = (const float4*)(y_s + (i * 7 + jx) * 20);
#pragma unroll
        for (int q = 0; q < 5; q++) {
            float4 yv = yrow[q];
            xa[4 * q + 0] = fmaxf(xa[4 * q + 0], 0.0f) * yv.x;
            xa[4 * q + 1] = fmaxf(xa[4 * q + 1], 0.0f) * yv.y;
            xa[4 * q + 2] = fmaxf(xa[4 * q + 2], 0.0f) * yv.z;
            xa[4 * q + 3] = fmaxf(xa[4 * q + 3], 0.0f) * yv.w;
        }

        float z2[20];
        {
            const float4* bzp = (const float4*)bz_s;
#pragma unroll
            for (int q = 0; q < 5; q++) {
                float4 v = bzp[q];
                z2[4 * q + 0] = v.x; z2[4 * q + 1] = v.y;
                z2[4 * q + 2] = v.z; z2[4 * q + 3] = v.w;
            }
        }
#pragma unroll
        for (int m = 0; m < 20; m++) {
            float v = xa[m];
            const float4* row = (const float4*)(wz_s + m * 20);
#pragma unroll
            for (int q = 0; q < 5; q++) {
                float4 w = row[q];
                z2[4 * q + 0] = fmaf(v, w.x, z2[4 * q + 0]);
                z2[4 * q + 1] = fmaf(v, w.y, z2[4 * q + 1]);
                z2[4 * q + 2] = fmaf(v, w.z, z2[4 * q + 2]);
                z2[4 * q + 3] = fmaf(v, w.w, z2[4 * q + 3]);
            }
        }

        float z3 = bo_s;
        const float4* wop = (const float4*)wo_s;
#pragma unroll
        for (int q = 0; q < 5; q++) {
            float4 w = wop[q];
            z3 = fmaf(fmaxf(z2[4 * q + 0], 0.0f), w.x, z3);
            z3 = fmaf(fmaxf(z2[4 * q + 1], 0.0f), w.y, z3);
            z3 = fmaf(fmaxf(z2[4 * q + 2], 0.0f), w.z, z3);
            z3 = fmaf(fmaxf(z2[4 * q + 3], 0.0f), w.w, z3);
        }
        sum += z3;
    }

    out[gid] = sum;
}

extern "C" void kernel_launch(void* const* d_in, const int* in_sizes, int n_in,
                              void* d_out, int out_size) {
    const float* feature   = (const float*)d_in[0];
    const float* history   = (const float*)d_in[1];
    const int*   relation  = (const int*)d_in[2];
    const int*   pfl       = (const int*)d_in[3];
    const float* emb_phase = (const float*)d_in[4];
    const float* w_veh     = (const float*)d_in[5];
    const float* b_veh     = (const float*)d_in[6];
    const float* w_hist    = (const float*)d_in[7];
    const float* b_hist    = (const float*)d_in[8];
    const float* wih       = (const float*)d_in[9];
    const float* whh       = (const float*)d_in[10];
    const float* bih       = (const float*)d_in[11];
    const float* bhh       = (const float*)d_in[12];
    const float* w_lane    = (const float*)d_in[13];
    const float* b_lane    = (const float*)d_in[14];
    const float* emb_const = (const float*)d_in[15];
    const float* wf        = (const float*)d_in[16];
    const float* bfv       = (const float*)d_in[17];
    const float* wc        = (const float*)d_in[18];
    const float* bc        = (const float*)d_in[19];
    const float* wz        = (const float*)d_in[20];
    const float* bz        = (const float*)d_in[21];
    const float* wo        = (const float*)d_in[22];
    const float* bo        = (const float*)d_in[23];

    const int total = B_TOT * P_LANES;            // 65536 threads
    const int blocks = total / 256;               // 256 blocks

    frap_kernel<<<blocks, 256>>>(feature, history, emb_phase, w_veh, b_veh,
                                 w_hist, b_hist, wih, whh, bih, bhh,
                                 w_lane, b_lane,
                                 wf, bfv, wc, bc, wz, bz, wo, bo,
                                 emb_const, relation, pfl, (float*)d_out);
}

// round 6
// speedup vs baseline: 1.3476x; 1.3476x over previous
#include <cuda_runtime.h>

#define B_TOT 8192
#define T_STEPS 128
#define P_LANES 8

// ---------------- packed f32x2 helpers ----------------
__device__ __forceinline__ unsigned long long pack2(float x, float y) {
    unsigned long long r;
    asm("mov.b64 %0, {%1, %2};" : "=l"(r) : "f"(x), "f"(y));
    return r;
}
__device__ __forceinline__ float2 unpack2(unsigned long long v) {
    float2 r;
    asm("mov.b64 {%0, %1}, %2;" : "=f"(r.x), "=f"(r.y) : "l"(v));
    return r;
}
__device__ __forceinline__ void ffma2(unsigned long long& d,
                                      unsigned long long a,
                                      unsigned long long b) {
    asm("fma.rn.f32x2 %0, %1, %2, %0;" : "+l"(d) : "l"(a), "l"(b));
}

// MUFU.TANH-based activations. Measured rel_err with approx sigmoid was
// 6.3e-8 (vs 1e-3 threshold) -> n gate also uses MUFU tanh; expected
// rel_err ~1e-5, still >=100x margin.
__device__ __forceinline__ float tanh_approx(float x) {
    float r;
    asm("tanh.approx.f32 %0, %1;" : "=f"(r) : "f"(x));
    return r;
}
__device__ __forceinline__ float sigmoidf(float x) {
    return fmaf(0.5f, tanh_approx(0.5f * x), 0.5f);
}

// =====================================================================
// Fused kernel: per-(b,p) GRU over T=128 + lane projection + pairwise
// competition MLP. All 8 lanes of a batch element live in one block;
// pressures cross the stage boundary through shared memory.
//
// GRU gate rows: 0..9 = r, 10..19 = z, 20..29 = n
// r,z combined: grz = [Wih_rz | Whh_rz] @ [x; h] + (bih+bhh)_rz
// n split:      inn = Wih_n x + bih_n,   hn = Whh_n h + bhh_n
// Weights column-major in smem; accumulators init'd from the bias column
// (LDS.128). Gates are processed inline (no r[]/z[] arrays) to stay
// under the 128-register cap without spilling. The x/h column loops are
// merged so each pack2 feeds both the rz and the n matmuls.
// =====================================================================
__global__ __launch_bounds__(256, 2) void frap_kernel(
    const float* __restrict__ feature,   // (B, 16)
    const float* __restrict__ history,   // (B, T, 24)
    const float* __restrict__ emb_phase, // (2,4)
    const float* __restrict__ w_veh,     // (1,4)
    const float* __restrict__ b_veh,     // (4)
    const float* __restrict__ w_hist,    // (3,4)
    const float* __restrict__ b_hist,    // (4)
    const float* __restrict__ wih,       // (30,4)
    const float* __restrict__ whh,       // (30,10)
    const float* __restrict__ bih,       // (30)
    const float* __restrict__ bhh,       // (30)
    const float* __restrict__ w_lane,    // (18,16)
    const float* __restrict__ b_lane,    // (16)
    const float* __restrict__ wf,        // (32,20)
    const float* __restrict__ bf,        // (20)
    const float* __restrict__ wc,        // (4,20)
    const float* __restrict__ bc,        // (20)
    const float* __restrict__ wz,        // (20,20)
    const float* __restrict__ bz,        // (20)
    const float* __restrict__ wo,        // (20,1)
    const float* __restrict__ bo,        // (1)
    const float* __restrict__ emb_const, // (2,4)
    const int*   __restrict__ relation,  // (8,7)
    const int*   __restrict__ pfl,       // (8)
    float* __restrict__ out)             // (B, 8)
{
    // --- GRU weights (col-major) ---
    __shared__ __align__(16) float wrz_s[15 * 20];  // cols: x0..3,h0..9,bias
    __shared__ __align__(16) float win_s[5 * 12];   // cols: x0..3,bias (pad 12)
    __shared__ __align__(16) float whn_s[11 * 12];  // cols: h0..9,bias (pad 12)
    __shared__ __align__(16) float wlane_s[18 * 16]; // pre-scaled by 2
    __shared__ __align__(16) float blane_s[16];      // pre-scaled by 2
    // --- pair-stage weights ---
    __shared__ __align__(16) float wf_s[32 * 20];
    __shared__ __align__(16) float wz_s[20 * 20];
    __shared__ __align__(16) float y_s[56 * 20];    // relu(const@wc+bc)
    __shared__ __align__(16) float bf_s[20];
    __shared__ __align__(16) float bz_s[20];
    __shared__ __align__(16) float wo_s[20];
    __shared__ int   pfl_s[8];
    __shared__ float bo_s;
    // --- cross-stage pressures, transposed [feature][thread] ---
    __shared__ float press_s[16][264];

    const int tid = threadIdx.x;

    for (int idx = tid; idx < 15 * 20; idx += 256) {
        int k = idx / 20, j = idx % 20;
        float v;
        if (k < 4)        v = wih[j * 4 + k];
        else if (k < 14)  v = whh[j * 10 + (k - 4)];
        else              v = bih[j] + bhh[j];
        wrz_s[idx] = v;
    }
    for (int idx = tid; idx < 5 * 12; idx += 256) {
        int k = idx / 12, i = idx % 12;
        float v = 0.0f;
        if (i < 10) v = (k < 4) ? wih[(20 + i) * 4 + k] : bih[20 + i];
        win_s[idx] = v;
    }
    for (int idx = tid; idx < 11 * 12; idx += 256) {
        int k = idx / 12, i = idx % 12;
        float v = 0.0f;
        if (i < 10) v = (k < 10) ? whh[(20 + i) * 10 + k] : bhh[20 + i];
        whn_s[idx] = v;
    }
    // pressure = 2*relu(proj) == relu(2*proj): fold the 2x into the weights
    for (int idx = tid; idx < 18 * 16; idx += 256) wlane_s[idx] = 2.0f * w_lane[idx];
    if (tid < 16) blane_s[tid] = 2.0f * b_lane[tid];

    for (int idx = tid; idx < 640; idx += 256) wf_s[idx] = wf[idx];
    for (int idx = tid; idx < 400; idx += 256) wz_s[idx] = wz[idx];
    if (tid < 20) { bf_s[tid] = bf[tid]; bz_s[tid] = bz[tid]; wo_s[tid] = wo[tid]; }
    if (tid < 8) pfl_s[tid] = pfl[tid];
    if (tid == 0) bo_s = bo[0];
    for (int idx = tid; idx < 56 * 20; idx += 256) {
        int pr = idx / 20, l = idx % 20;
        int rel = relation[pr];
        float a = bc[l];
        a = fmaf(emb_const[rel * 4 + 0], wc[0 * 20 + l], a);
        a = fmaf(emb_const[rel * 4 + 1], wc[1 * 20 + l], a);
        a = fmaf(emb_const[rel * 4 + 2], wc[2 * 20 + l], a);
        a = fmaf(emb_const[rel * 4 + 3], wc[3 * 20 + l], a);
        y_s[idx] = fmaxf(a, 0.0f);
    }
    __syncthreads();

    const int gid = blockIdx.x * 256 + tid;
    const int b = gid >> 3;
    const int p = gid & 7;

    // per-thread uniform params (broadcast loads, L1-resident)
    float wh0[4], wh1[4], wh2[4], bh[4];
#pragma unroll
    for (int k = 0; k < 4; k++) {
        wh0[k] = __ldg(&w_hist[k]);
        wh1[k] = __ldg(&w_hist[4 + k]);
        wh2[k] = __ldg(&w_hist[8 + k]);
        bh[k]  = __ldg(&b_hist[k]);
    }

    // feature scalars only — f_phase/f_veh computed after the loop (reg trim)
    const int   pbit = (int)feature[b * 16 + p];
    const float veh  = feature[b * 16 + 8 + p];

    float h[10];
#pragma unroll
    for (int i = 0; i < 10; i++) h[i] = 0.0f;

    const float* hp = history + (size_t)b * T_STEPS * 24 + p;
    float c0 = hp[0], c1 = hp[8], c2 = hp[16];

#pragma unroll 1
    for (int t = 0; t < T_STEPS; t++) {
        float n0 = 0.f, n1 = 0.f, n2 = 0.f;
        if (t + 1 < T_STEPS) {
            const float* q = hp + 24;
            n0 = q[0]; n1 = q[8]; n2 = q[16];
            hp = q;
        }

        // x_t = sigmoid(hist3 @ w_hist + b_hist)
        float x[4];
#pragma unroll
        for (int k = 0; k < 4; k++)
            x[k] = sigmoidf(fmaf(c2, wh2[k],
                            fmaf(c1, wh1[k],
                            fmaf(c0, wh0[k], bh[k]))));

        // ---- accumulators: bias-init via LDS.128 ----
        unsigned long long arz[10];  // 20 r,z outputs
        unsigned long long ain[6];   // 10 inn outputs (pad 12)
        unsigned long long ahn[6];   // 10 hn outputs (pad 12)
        {
            const ulonglong2* bcol = (const ulonglong2*)(wrz_s + 14 * 20);
#pragma unroll
            for (int m = 0; m < 5; m++) {
                ulonglong2 v = bcol[m];
                arz[2 * m] = v.x; arz[2 * m + 1] = v.y;
            }
            const ulonglong2* bi  = (const ulonglong2*)(win_s + 4 * 12);
            const ulonglong2* bhp = (const ulonglong2*)(whn_s + 10 * 12);
#pragma unroll
            for (int m = 0; m < 3; m++) {
                ulonglong2 v1 = bi[m];
                ain[2 * m] = v1.x; ain[2 * m + 1] = v1.y;
                ulonglong2 v2 = bhp[m];
                ahn[2 * m] = v2.x; ahn[2 * m + 1] = v2.y;
            }
        }

        // ---- x columns: feed arz (wrz cols 0..3) and ain (win cols 0..3) ----
#pragma unroll
        for (int k = 0; k < 4; k++) {
            unsigned long long vv = pack2(x[k], x[k]);
            const ulonglong2* colA = (const ulonglong2*)(wrz_s + k * 20);
#pragma unroll
            for (int m = 0; m < 5; m++) {
                ulonglong2 w = colA[m];
                ffma2(arz[2 * m],     w.x, vv);
                ffma2(arz[2 * m + 1], w.y, vv);
            }
            const ulonglong2* colB = (const ulonglong2*)(win_s + k * 12);
#pragma unroll
            for (int m = 0; m < 3; m++) {
                ulonglong2 w = colB[m];
                ffma2(ain[2 * m],     w.x, vv);
                ffma2(ain[2 * m + 1], w.y, vv);
            }
        }

        // ---- h columns: feed arz (wrz cols 4..13) and ahn (whn cols 0..9) ----
#pragma unroll
        for (int k = 0; k < 10; k++) {
            unsigned long long vv = pack2(h[k], h[k]);
            const ulonglong2* colA = (const ulonglong2*)(wrz_s + (4 + k) * 20);
#pragma unroll
            for (int m = 0; m < 5; m++) {
                ulonglong2 w = colA[m];
                ffma2(arz[2 * m],     w.x, vv);
                ffma2(arz[2 * m + 1], w.y, vv);
            }
            const ulonglong2* colB = (const ulonglong2*)(whn_s + k * 12);
#pragma unroll
            for (int m = 0; m < 3; m++) {
                ulonglong2 w = colB[m];
                ffma2(ahn[2 * m],     w.x, vv);
                ffma2(ahn[2 * m + 1], w.y, vv);
            }
        }

        // ---- gates, processed inline (no persistent r/z arrays) ----
#pragma unroll
        for (int m = 0; m < 5; m++) {
            float2 ar = unpack2(arz[m]);         // (r_{2m}, r_{2m+1})
            float2 az = unpack2(arz[5 + m]);     // (z_{2m}, z_{2m+1})
            float2 gi = unpack2(ain[m]);         // (inn_{2m}, inn_{2m+1})
            float2 gh = unpack2(ahn[m]);         // (hn_{2m},  hn_{2m+1})
            float r0 = sigmoidf(ar.x);
            float r1 = sigmoidf(ar.y);
            float z0 = sigmoidf(az.x);
            float z1 = sigmoidf(az.y);
            float nn0 = tanh_approx(fmaf(r0, gh.x, gi.x));
            float nn1 = tanh_approx(fmaf(r1, gh.y, gi.y));
            // h' = n + z*(h - n)
            h[2 * m]     = fmaf(z0, h[2 * m]     - nn0, nn0);
            h[2 * m + 1] = fmaf(z1, h[2 * m + 1] - nn1, nn1);
        }

        c0 = n0; c1 = n1; c2 = n2;
    }

    // ---- lane projection: relu([f_veh, f_phase, h] @ (2*w_lane) + 2*b_lane) ----
    {
        float lf[18];
#pragma unroll
        for (int k = 0; k < 4; k++) {
            lf[k]     = sigmoidf(fmaf(veh, __ldg(&w_veh[k]), __ldg(&b_veh[k])));
            lf[4 + k] = sigmoidf(__ldg(&emb_phase[pbit * 4 + k]));
        }
#pragma unroll
        for (int i = 0; i < 10; i++) lf[8 + i] = h[i];

        float acc[16];
#pragma unroll
        for (int l = 0; l < 16; l++) acc[l] = blane_s[l];
#pragma unroll
        for (int m = 0; m < 18; m++) {
            float v = lf[m];
            const float4* row = (const float4*)(wlane_s + m * 16);
#pragma unroll
            for (int q = 0; q < 4; q++) {
                float4 w = row[q];
                acc[4 * q + 0] = fmaf(v, w.x, acc[4 * q + 0]);
                acc[4 * q + 1] = fmaf(v, w.y, acc[4 * q + 1]);
                acc[4 * q + 2] = fmaf(v, w.z, acc[4 * q + 2]);
                acc[4 * q + 3] = fmaf(v, w.w, acc[4 * q + 3]);
            }
        }
        // transposed store: conflict-free (lane-consecutive per feature l)
#pragma unroll
        for (int l = 0; l < 16; l++)
            press_s[l][tid] = fmaxf(acc[l], 0.0f);
    }
    __syncthreads();

    // =================== pairwise competition stage ===================
    const int i = p;
    const int rowbase = tid & 0xF8;   // this thread's batch-row base in press_s

    float pi[16];
    {
        const int ci = rowbase + pfl_s[i];
#pragma unroll
        for (int l = 0; l < 16; l++) pi[l] = press_s[l][ci];
    }

    float sum = 0.0f;
#pragma unroll 1
    for (int jx = 0; jx < 7; jx++) {
        const int j = jx + (jx >= i ? 1 : 0);
        float pj[16];
        {
            const int cj = rowbase + pfl_s[j];
#pragma unroll
            for (int l = 0; l < 16; l++) pj[l] = press_s[l][cj];
        }

        float xa[20];
        {
            const float4* bfp = (const float4*)bf_s;
#pragma unroll
            for (int q = 0; q < 5; q++) {
                float4 v = bfp[q];
                xa[4 * q + 0] = v.x; xa[4 * q + 1] = v.y;
                xa[4 * q + 2] = v.z; xa[4 * q + 3] = v.w;
            }
        }
#pragma unroll
        for (int m = 0; m < 16; m++) {
            float v = pi[m];
            const float4* row = (const float4*)(wf_s + m * 20);
#pragma unroll
            for (int q = 0; q < 5; q++) {
                float4 w = row[q];
                xa[4 * q + 0] = fmaf(v, w.x, xa[4 * q + 0]);
                xa[4 * q + 1] = fmaf(v, w.y, xa[4 * q + 1]);
                xa[4 * q + 2] = fmaf(v, w.z, xa[4 * q + 2]);
                xa[4 * q + 3] = fmaf(v, w.w, xa[4 * q + 3]);
            }
        }
#pragma unroll
        for (int m = 0; m < 16; m++) {
            float v = pj[m];
            const float4* row = (const float4*)(wf_s + (16 + m) * 20);
#pragma unroll
            for (int q = 0; q < 5; q++) {
                float4 w = row[q];
                xa[4 * q + 0] = fmaf(v, w.x, xa[4 * q + 0]);
                xa[4 * q + 1] = fmaf(v, w.y, xa[4 * q + 1]);
                xa[4 * q + 2] = fmaf(v, w.z, xa[4 * q + 2]);
                xa[4 * q + 3] = fmaf(v, w.w, xa[4 * q + 3]);
            }
        }

        // xa = relu(xa) * y[i][jx]
        const float4* yrow = (const float4*)(y_s + (i * 7 + jx) * 20);
#pragma unroll
        for (int q = 0; q < 5; q++) {
            float4 yv = yrow[q];
            xa[4 * q + 0] = fmaxf(xa[4 * q + 0], 0.0f) * yv.x;
            xa[4 * q + 1] = fmaxf(xa[4 * q + 1], 0.0f) * yv.y;
            xa[4 * q + 2] = fmaxf(xa[4 * q + 2], 0.0f) * yv.z;
            xa[4 * q + 3] = fmaxf(xa[4 * q + 3], 0.0f) * yv.w;
        }

        float z2[20];
        {
            const float4* bzp = (const float4*)bz_s;
#pragma unroll
            for (int q = 0; q < 5; q++) {
                float4 v = bzp[q];
                z2[4 * q + 0] = v.x; z2[4 * q + 1] = v.y;
                z2[4 * q + 2] = v.z; z2[4 * q + 3] = v.w;
            }
        }
#pragma unroll
        for (int m = 0; m < 20; m++) {
            float v = xa[m];
            const float4* row = (const float4*)(wz_s + m * 20);
#pragma unroll
            for (int q = 0; q < 5; q++) {
                float4 w = row[q];
                z2[4 * q + 0] = fmaf(v, w.x, z2[4 * q + 0]);
                z2[4 * q + 1] = fmaf(v, w.y, z2[4 * q + 1]);
                z2[4 * q + 2] = fmaf(v, w.z, z2[4 * q + 2]);
                z2[4 * q + 3] = fmaf(v, w.w, z2[4 * q + 3]);
            }
        }

        float z3 = bo_s;
        const float4* wop = (const float4*)wo_s;
#pragma unroll
        for (int q = 0; q < 5; q++) {
            float4 w = wop[q];
            z3 = fmaf(fmaxf(z2[4 * q + 0], 0.0f), w.x, z3);
            z3 = fmaf(fmaxf(z2[4 * q + 1], 0.0f), w.y, z3);
            z3 = fmaf(fmaxf(z2[4 * q + 2], 0.0f), w.z, z3);
            z3 = fmaf(fmaxf(z2[4 * q + 3], 0.0f), w.w, z3);
        }
        sum += z3;
    }

    out[gid] = sum;
}

extern "C" void kernel_launch(void* const* d_in, const int* in_sizes, int n_in,
                              void* d_out, int out_size) {
    const float* feature   = (const float*)d_in[0];
    const float* history   = (const float*)d_in[1];
    const int*   relation  = (const int*)d_in[2];
    const int*   pfl       = (const int*)d_in[3];
    const float* emb_phase = (const float*)d_in[4];
    const float* w_veh     = (const float*)d_in[5];
    const float* b_veh     = (const float*)d_in[6];
    const float* w_hist    = (const float*)d_in[7];
    const float* b_hist    = (const float*)d_in[8];
    const float* wih       = (const float*)d_in[9];
    const float* whh       = (const float*)d_in[10];
    const float* bih       = (const float*)d_in[11];
    const float* bhh       = (const float*)d_in[12];
    const float* w_lane    = (const float*)d_in[13];
    const float* b_lane    = (const float*)d_in[14];
    const float* emb_const = (const float*)d_in[15];
    const float* wf        = (const float*)d_in[16];
    const float* bfv       = (const float*)d_in[17];
    const float* wc        = (const float*)d_in[18];
    const float* bc        = (const float*)d_in[19];
    const float* wz        = (const float*)d_in[20];
    const float* bz        = (const float*)d_in[21];
    const float* wo        = (const float*)d_in[22];
    const float* bo        = (const float*)d_in[23];

    const int total = B_TOT * P_LANES;            // 65536 threads
    const int blocks = total / 256;               // 256 blocks

    frap_kernel<<<blocks, 256>>>(feature, history, emb_phase, w_veh, b_veh,
                                 w_hist, b_hist, wih, whh, bih, bhh,
                                 w_lane, b_lane,
                                 wf, bfv, wc, bc, wz, bz, wo, bo,
                                 emb_const, relation, pfl, (float*)d_out);
}

// round 11
// speedup vs baseline: 1.3826x; 1.0260x over previous
#include <cuda_runtime.h>

#define B_TOT 8192
#define T_STEPS 128
#define P_LANES 8

// ---------------- packed f32x2 helpers ----------------
__device__ __forceinline__ unsigned long long pack2(float x, float y) {
    unsigned long long r;
    asm("mov.b64 %0, {%1, %2};" : "=l"(r) : "f"(x), "f"(y));
    return r;
}
__device__ __forceinline__ float2 unpack2(unsigned long long v) {
    float2 r;
    asm("mov.b64 {%0, %1}, %2;" : "=f"(r.x), "=f"(r.y) : "l"(v));
    return r;
}
__device__ __forceinline__ void ffma2(unsigned long long& d,
                                      unsigned long long a,
                                      unsigned long long b) {
    asm("fma.rn.f32x2 %0, %1, %2, %0;" : "+l"(d) : "l"(a), "l"(b));
}

// MUFU.TANH-based activations (measured rel_err 6.3e-8 vs 1e-3 threshold).
__device__ __forceinline__ float tanh_approx(float x) {
    float r;
    asm("tanh.approx.f32 %0, %1;" : "=f"(r) : "f"(x));
    return r;
}
__device__ __forceinline__ float sigmoidf(float x) {
    return fmaf(0.5f, tanh_approx(0.5f * x), 0.5f);
}

// 10-wide f32x2 accumulator helpers: 10 consecutive floats at a 16B-aligned
// smem base -> 2x LDS.128 + 1x LDS.64, 5 accumulators.
__device__ __forceinline__ void load10(unsigned long long a[5], const float* base) {
    const ulonglong2* p = (const ulonglong2*)base;
    ulonglong2 t0 = p[0], t1 = p[1];
    a[0] = t0.x; a[1] = t0.y; a[2] = t1.x; a[3] = t1.y;
    a[4] = *(const unsigned long long*)(base + 8);
}
__device__ __forceinline__ void fma10(unsigned long long a[5], const float* base,
                                      unsigned long long vv) {
    const ulonglong2* p = (const ulonglong2*)base;
    ulonglong2 t0 = p[0], t1 = p[1];
    unsigned long long t2 = *(const unsigned long long*)(base + 8);
    ffma2(a[0], t0.x, vv);
    ffma2(a[1], t0.y, vv);
    ffma2(a[2], t1.x, vv);
    ffma2(a[3], t1.y, vv);
    ffma2(a[4], t2, vv);
}

// =====================================================================
// Fused kernel: per-(b,p) GRU over T=128 + lane projection + pairwise
// competition MLP. Two-pass gate computation to cap register pressure:
//   pass 1: r, inn, hn  -> n = tanh(inn + sigmoid(r)*hn)   (30 acc regs)
//   pass 2: z           -> h' = n + sigmoid(z)*(h - n)     (10 acc regs)
// wrz_s column layout: [r rows 0..9, pad2, z rows 0..9, pad2] (stride 24)
// so each pass reads only its half (same total LDS bytes as single-pass).
// =====================================================================
__global__ __launch_bounds__(256, 2) void frap_kernel(
    const float* __restrict__ feature,   // (B, 16)
    const float* __restrict__ history,   // (B, T, 24)
    const float* __restrict__ emb_phase, // (2,4)
    const float* __restrict__ w_veh,     // (1,4)
    const float* __restrict__ b_veh,     // (4)
    const float* __restrict__ w_hist,    // (3,4)
    const float* __restrict__ b_hist,    // (4)
    const float* __restrict__ wih,       // (30,4)
    const float* __restrict__ whh,       // (30,10)
    const float* __restrict__ bih,       // (30)
    const float* __restrict__ bhh,       // (30)
    const float* __restrict__ w_lane,    // (18,16)
    const float* __restrict__ b_lane,    // (16)
    const float* __restrict__ wf,        // (32,20)
    const float* __restrict__ bf,        // (20)
    const float* __restrict__ wc,        // (4,20)
    const float* __restrict__ bc,        // (20)
    const float* __restrict__ wz,        // (20,20)
    const float* __restrict__ bz,        // (20)
    const float* __restrict__ wo,        // (20,1)
    const float* __restrict__ bo,        // (1)
    const float* __restrict__ emb_const, // (2,4)
    const int*   __restrict__ relation,  // (8,7)
    const int*   __restrict__ pfl,       // (8)
    float* __restrict__ out)             // (B, 8)
{
    // --- GRU weights (col-major) ---
    // wrz_s: 15 cols (x0..3, h0..9, bias) x 24 rows: [r0..r9,pad2,z0..z9,pad2]
    __shared__ __align__(16) float wrz_s[15 * 24];
    __shared__ __align__(16) float win_s[5 * 12];   // cols x0..3,bias; rows n0..9,pad2
    __shared__ __align__(16) float whn_s[11 * 12];  // cols h0..9,bias; rows n0..9,pad2
    __shared__ __align__(16) float wlane_s[18 * 16]; // pre-scaled by 2
    __shared__ __align__(16) float blane_s[16];      // pre-scaled by 2
    // --- pair-stage weights ---
    __shared__ __align__(16) float wf_s[32 * 20];
    __shared__ __align__(16) float wz_s[20 * 20];
    __shared__ __align__(16) float y_s[56 * 20];    // relu(const@wc+bc)
    __shared__ __align__(16) float bf_s[20];
    __shared__ __align__(16) float bz_s[20];
    __shared__ __align__(16) float wo_s[20];
    __shared__ int   pfl_s[8];
    __shared__ float bo_s;
    // --- cross-stage pressures, transposed [feature][thread] ---
    __shared__ float press_s[16][264];

    const int tid = threadIdx.x;

    // wrz_s fill: r rows at 0..9, z rows at 12..21, pads zeroed
    for (int idx = tid; idx < 15 * 24; idx += 256) {
        int k = idx / 24, r = idx % 24;
        int j = -1;
        if (r < 10)                 j = r;           // r-gate rows 0..9
        else if (r >= 12 && r < 22) j = r - 12 + 10; // z-gate rows 10..19
        float v = 0.0f;
        if (j >= 0) {
            if (k < 4)        v = wih[j * 4 + k];
            else if (k < 14)  v = whh[j * 10 + (k - 4)];
            else              v = bih[j] + bhh[j];
        }
        wrz_s[idx] = v;
    }
    for (int idx = tid; idx < 5 * 12; idx += 256) {
        int k = idx / 12, i = idx % 12;
        float v = 0.0f;
        if (i < 10) v = (k < 4) ? wih[(20 + i) * 4 + k] : bih[20 + i];
        win_s[idx] = v;
    }
    for (int idx = tid; idx < 11 * 12; idx += 256) {
        int k = idx / 12, i = idx % 12;
        float v = 0.0f;
        if (i < 10) v = (k < 10) ? whh[(20 + i) * 10 + k] : bhh[20 + i];
        whn_s[idx] = v;
    }
    // pressure = 2*relu(proj) == relu(2*proj): fold the 2x into the weights
    for (int idx = tid; idx < 18 * 16; idx += 256) wlane_s[idx] = 2.0f * w_lane[idx];
    if (tid < 16) blane_s[tid] = 2.0f * b_lane[tid];

    for (int idx = tid; idx < 640; idx += 256) wf_s[idx] = wf[idx];
    for (int idx = tid; idx < 400; idx += 256) wz_s[idx] = wz[idx];
    if (tid < 20) { bf_s[tid] = bf[tid]; bz_s[tid] = bz[tid]; wo_s[tid] = wo[tid]; }
    if (tid < 8) pfl_s[tid] = pfl[tid];
    if (tid == 0) bo_s = bo[0];
    for (int idx = tid; idx < 56 * 20; idx += 256) {
        int pr = idx / 20, l = idx % 20;
        int rel = relation[pr];
        float a = bc[l];
        a = fmaf(emb_const[rel * 4 + 0], wc[0 * 20 + l], a);
        a = fmaf(emb_const[rel * 4 + 1], wc[1 * 20 + l], a);
        a = fmaf(emb_const[rel * 4 + 2], wc[2 * 20 + l], a);
        a = fmaf(emb_const[rel * 4 + 3], wc[3 * 20 + l], a);
        y_s[idx] = fmaxf(a, 0.0f);
    }
    __syncthreads();

    const int gid = blockIdx.x * 256 + tid;
    const int b = gid >> 3;
    const int p = gid & 7;

    // per-thread uniform params (broadcast loads, L1-resident)
    float wh0[4], wh1[4], wh2[4], bh[4];
#pragma unroll
    for (int k = 0; k < 4; k++) {
        wh0[k] = __ldg(&w_hist[k]);
        wh1[k] = __ldg(&w_hist[4 + k]);
        wh2[k] = __ldg(&w_hist[8 + k]);
        bh[k]  = __ldg(&b_hist[k]);
    }

    const int   pbit = (int)feature[b * 16 + p];
    const float veh  = feature[b * 16 + 8 + p];

    float h[10];
#pragma unroll
    for (int i = 0; i < 10; i++) h[i] = 0.0f;

    const float* hp = history + (size_t)b * T_STEPS * 24 + p;
    float c0 = hp[0], c1 = hp[8], c2 = hp[16];

#pragma unroll 1
    for (int t = 0; t < T_STEPS; t++) {
        float n0 = 0.f, n1 = 0.f, n2 = 0.f;
        if (t + 1 < T_STEPS) {
            const float* q = hp + 24;
            n0 = q[0]; n1 = q[8]; n2 = q[16];
            hp = q;
        }

        // x_t = sigmoid(hist3 @ w_hist + b_hist)
        float x[4];
#pragma unroll
        for (int k = 0; k < 4; k++)
            x[k] = sigmoidf(fmaf(c2, wh2[k],
                            fmaf(c1, wh1[k],
                            fmaf(c0, wh0[k], bh[k]))));

        float ng[10];   // n gate result, carried into pass 2
        // ================= pass 1: r, inn, hn -> n =================
        {
            unsigned long long ar[5], ain[5], ahn[5];
            load10(ar,  wrz_s + 14 * 24);       // r-half of bias col
            load10(ain, win_s + 4 * 12);
            load10(ahn, whn_s + 10 * 12);
#pragma unroll
            for (int k = 0; k < 4; k++) {
                unsigned long long vv = pack2(x[k], x[k]);
                fma10(ar,  wrz_s + k * 24, vv);
                fma10(ain, win_s + k * 12, vv);
            }
#pragma unroll
            for (int k = 0; k < 10; k++) {
                unsigned long long vv = pack2(h[k], h[k]);
                fma10(ar,  wrz_s + (4 + k) * 24, vv);
                fma10(ahn, whn_s + k * 12, vv);
            }
#pragma unroll
            for (int m = 0; m < 5; m++) {
                float2 rr = unpack2(ar[m]);
                float2 gi = unpack2(ain[m]);
                float2 gh = unpack2(ahn[m]);
                ng[2 * m]     = tanh_approx(fmaf(sigmoidf(rr.x), gh.x, gi.x));
                ng[2 * m + 1] = tanh_approx(fmaf(sigmoidf(rr.y), gh.y, gi.y));
            }
        }
        // ================= pass 2: z -> h update =================
        {
            unsigned long long az[5];
            load10(az, wrz_s + 14 * 24 + 12);   // z-half of bias col
#pragma unroll
            for (int k = 0; k < 4; k++) {
                unsigned long long vv = pack2(x[k], x[k]);
                fma10(az, wrz_s + k * 24 + 12, vv);
            }
#pragma unroll
            for (int k = 0; k < 10; k++) {
                unsigned long long vv = pack2(h[k], h[k]);
                fma10(az, wrz_s + (4 + k) * 24 + 12, vv);
            }
#pragma unroll
            for (int m = 0; m < 5; m++) {
                float2 zz = unpack2(az[m]);
                float z0 = sigmoidf(zz.x);
                float z1 = sigmoidf(zz.y);
                // h' = n + z*(h - n)
                h[2 * m]     = fmaf(z0, h[2 * m]     - ng[2 * m],     ng[2 * m]);
                h[2 * m + 1] = fmaf(z1, h[2 * m + 1] - ng[2 * m + 1], ng[2 * m + 1]);
            }
        }

        c0 = n0; c1 = n1; c2 = n2;
    }

    // ---- lane projection: relu([f_veh, f_phase, h] @ (2*w_lane) + 2*b_lane) ----
    {
        float lf[18];
#pragma unroll
        for (int k = 0; k < 4; k++) {
            lf[k]     = sigmoidf(fmaf(veh, __ldg(&w_veh[k]), __ldg(&b_veh[k])));
            lf[4 + k] = sigmoidf(__ldg(&emb_phase[pbit * 4 + k]));
        }
#pragma unroll
        for (int i = 0; i < 10; i++) lf[8 + i] = h[i];

        float acc[16];
#pragma unroll
        for (int l = 0; l < 16; l++) acc[l] = blane_s[l];
#pragma unroll
        for (int m = 0; m < 18; m++) {
            float v = lf[m];
            const float4* row = (const float4*)(wlane_s + m * 16);
#pragma unroll
            for (int q = 0; q < 4; q++) {
                float4 w = row[q];
                acc[4 * q + 0] = fmaf(v, w.x, acc[4 * q + 0]);
                acc[4 * q + 1] = fmaf(v, w.y, acc[4 * q + 1]);
                acc[4 * q + 2] = fmaf(v, w.z, acc[4 * q + 2]);
                acc[4 * q + 3] = fmaf(v, w.w, acc[4 * q + 3]);
            }
        }
        // transposed store: conflict-free (lane-consecutive per feature l)
#pragma unroll
        for (int l = 0; l < 16; l++)
            press_s[l][tid] = fmaxf(acc[l], 0.0f);
    }
    __syncthreads();

    // =================== pairwise competition stage ===================
    const int i = p;
    const int rowbase = tid & 0xF8;   // this thread's batch-row base in press_s

    float pi[16];
    {
        const int ci = rowbase + pfl_s[i];
#pragma unroll
        for (int l = 0; l < 16; l++) pi[l] = press_s[l][ci];
    }

    float sum = 0.0f;
#pragma unroll 1
    for (int jx = 0; jx < 7; jx++) {
        const int j = jx + (jx >= i ? 1 : 0);
        float pj[16];
        {
            const int cj = rowbase + pfl_s[j];
#pragma unroll
            for (int l = 0; l < 16; l++) pj[l] = press_s[l][cj];
        }

        float xa[20];
        {
            const float4* bfp = (const float4*)bf_s;
#pragma unroll
            for (int q = 0; q < 5; q++) {
                float4 v = bfp[q];
                xa[4 * q + 0] = v.x; xa[4 * q + 1] = v.y;
                xa[4 * q + 2] = v.z; xa[4 * q + 3] = v.w;
            }
        }
#pragma unroll
        for (int m = 0; m < 16; m++) {
            float v = pi[m];
            const float4* row = (const float4*)(wf_s + m * 20);
#pragma unroll
            for (int q = 0; q < 5; q++) {
                float4 w = row[q];
                xa[4 * q + 0] = fmaf(v, w.x, xa[4 * q + 0]);
                xa[4 * q + 1] = fmaf(v, w.y, xa[4 * q + 1]);
                xa[4 * q + 2] = fmaf(v, w.z, xa[4 * q + 2]);
                xa[4 * q + 3] = fmaf(v, w.w, xa[4 * q + 3]);
            }
        }
#pragma unroll
        for (int m = 0; m < 16; m++) {
            float v = pj[m];
            const float4* row = (const float4*)(wf_s + (16 + m) * 20);
#pragma unroll
            for (int q = 0; q < 5; q++) {
                float4 w = row[q];
                xa[4 * q + 0] = fmaf(v, w.x, xa[4 * q + 0]);
                xa[4 * q + 1] = fmaf(v, w.y, xa[4 * q + 1]);
                xa[4 * q + 2] = fmaf(v, w.z, xa[4 * q + 2]);
                xa[4 * q + 3] = fmaf(v, w.w, xa[4 * q + 3]);
            }
        }

        // xa = relu(xa) * y[i][jx]
        const float4* yrow = (const float4*)(y_s + (i * 7 + jx) * 20);
#pragma unroll
        for (int q = 0; q < 5; q++) {
            float4 yv = yrow[q];
            xa[4 * q + 0] = fmaxf(xa[4 * q + 0], 0.0f) * yv.x;
            xa[4 * q + 1] = fmaxf(xa[4 * q + 1], 0.0f) * yv.y;
            xa[4 * q + 2] = fmaxf(xa[4 * q + 2], 0.0f) * yv.z;
            xa[4 * q + 3] = fmaxf(xa[4 * q + 3], 0.0f) * yv.w;
        }

        float z2[20];
        {
            const float4* bzp = (const float4*)bz_s;
#pragma unroll
            for (int q = 0; q < 5; q++) {
                float4 v = bzp[q];
                z2[4 * q + 0] = v.x; z2[4 * q + 1] = v.y;
                z2[4 * q + 2] = v.z; z2[4 * q + 3] = v.w;
            }
        }
#pragma unroll
        for (int m = 0; m < 20; m++) {
            float v = xa[m];
            const float4* row = (const float4*)(wz_s + m * 20);
#pragma unroll
            for (int q = 0; q < 5; q++) {
                float4 w = row[q];
                z2[4 * q + 0] = fmaf(v, w.x, z2[4 * q + 0]);
                z2[4 * q + 1] = fmaf(v, w.y, z2[4 * q + 1]);
                z2[4 * q + 2] = fmaf(v, w.z, z2[4 * q + 2]);
                z2[4 * q + 3] = fmaf(v, w.w, z2[4 * q + 3]);
            }
        }

        float z3 = bo_s;
        const float4* wop = (const float4*)wo_s;
#pragma unroll
        for (int q = 0; q < 5; q++) {
            float4 w = wop[q];
            z3 = fmaf(fmaxf(z2[4 * q + 0], 0.0f), w.x, z3);
            z3 = fmaf(fmaxf(z2[4 * q + 1], 0.0f), w.y, z3);
            z3 = fmaf(fmaxf(z2[4 * q + 2], 0.0f), w.z, z3);
            z3 = fmaf(fmaxf(z2[4 * q + 3], 0.0f), w.w, z3);
        }
        sum += z3;
    }

    out[gid] = sum;
}

extern "C" void kernel_launch(void* const* d_in, const int* in_sizes, int n_in,
                              void* d_out, int out_size) {
    const float* feature   = (const float*)d_in[0];
    const float* history   = (const float*)d_in[1];
    const int*   relation  = (const int*)d_in[2];
    const int*   pfl       = (const int*)d_in[3];
    const float* emb_phase = (const float*)d_in[4];
    const float* w_veh     = (const float*)d_in[5];
    const float* b_veh     = (const float*)d_in[6];
    const float* w_hist    = (const float*)d_in[7];
    const float* b_hist    = (const float*)d_in[8];
    const float* wih       = (const float*)d_in[9];
    const float* whh       = (const float*)d_in[10];
    const float* bih       = (const float*)d_in[11];
    const float* bhh       = (const float*)d_in[12];
    const float* w_lane    = (const float*)d_in[13];
    const float* b_lane    = (const float*)d_in[14];
    const float* emb_const = (const float*)d_in[15];
    const float* wf        = (const float*)d_in[16];
    const float* bfv       = (const float*)d_in[17];
    const float* wc        = (const float*)d_in[18];
    const float* bc        = (const float*)d_in[19];
    const float* wz        = (const float*)d_in[20];
    const float* bz        = (const float*)d_in[21];
    const float* wo        = (const float*)d_in[22];
    const float* bo        = (const float*)d_in[23];

    const int total = B_TOT * P_LANES;            // 65536 threads
    const int blocks = total / 256;               // 256 blocks

    frap_kernel<<<blocks, 256>>>(feature, history, emb_phase, w_veh, b_veh,
                                 w_hist, b_hist, wih, whh, bih, bhh,
                                 w_lane, b_lane,
                                 wf, bfv, wc, bc, wz, bz, wo, bo,
                                 emb_const, relation, pfl, (float*)d_out);
}

// round 13
// speedup vs baseline: 1.6999x; 1.2295x over previous
#include <cuda_runtime.h>

#define B_TOT 8192
#define T_STEPS 128
#define P_LANES 8
#define NTHR 128

// ---------------- packed f32x2 helpers ----------------
__device__ __forceinline__ unsigned long long pack2(float x, float y) {
    unsigned long long r;
    asm("mov.b64 %0, {%1, %2};" : "=l"(r) : "f"(x), "f"(y));
    return r;
}
__device__ __forceinline__ float2 unpack2(unsigned long long v) {
    float2 r;
    asm("mov.b64 {%0, %1}, %2;" : "=f"(r.x), "=f"(r.y) : "l"(v));
    return r;
}
__device__ __forceinline__ void ffma2(unsigned long long& d,
                                      unsigned long long a,
                                      unsigned long long b) {
    asm("fma.rn.f32x2 %0, %1, %2, %0;" : "+l"(d) : "l"(a), "l"(b));
}

// MUFU.TANH-based activations (measured rel_err 6.3e-8 vs 1e-3 threshold).
__device__ __forceinline__ float tanh_approx(float x) {
    float r;
    asm("tanh.approx.f32 %0, %1;" : "=f"(r) : "f"(x));
    return r;
}
__device__ __forceinline__ float sigmoidf(float x) {
    return fmaf(0.5f, tanh_approx(0.5f * x), 0.5f);
}

// 10-wide f32x2 accumulator helpers: 10 consecutive floats at a 16B-aligned
// smem base -> 2x LDS.128 + 1x LDS.64, 5 accumulators.
__device__ __forceinline__ void load10(unsigned long long a[5], const float* base) {
    const ulonglong2* p = (const ulonglong2*)base;
    ulonglong2 t0 = p[0], t1 = p[1];
    a[0] = t0.x; a[1] = t0.y; a[2] = t1.x; a[3] = t1.y;
    a[4] = *(const unsigned long long*)(base + 8);
}
__device__ __forceinline__ void fma10(unsigned long long a[5], const float* base,
                                      unsigned long long vv) {
    const ulonglong2* p = (const ulonglong2*)base;
    ulonglong2 t0 = p[0], t1 = p[1];
    unsigned long long t2 = *(const unsigned long long*)(base + 8);
    ffma2(a[0], t0.x, vv);
    ffma2(a[1], t0.y, vv);
    ffma2(a[2], t1.x, vv);
    ffma2(a[3], t1.y, vv);
    ffma2(a[4], t2, vv);
}

// =====================================================================
// Fused kernel: per-(b,p) GRU over T=128 + lane projection + pairwise
// competition MLP. 128-thread blocks with __launch_bounds__(128, 3):
// 170-register cap so the GRU loop fits WITHOUT local-memory spills
// (measured: at the 128-reg cap ptxas spills ~0.7KB/thread/step ->
// 5.6GB DRAM traffic and 37% DRAM-active).
// Two-pass gates: pass 1 computes r/inn/hn -> n (30 acc regs),
// pass 2 computes z -> h update (10 acc regs).
// =====================================================================
__global__ __launch_bounds__(NTHR, 3) void frap_kernel(
    const float* __restrict__ feature,   // (B, 16)
    const float* __restrict__ history,   // (B, T, 24)
    const float* __restrict__ emb_phase, // (2,4)
    const float* __restrict__ w_veh,     // (1,4)
    const float* __restrict__ b_veh,     // (4)
    const float* __restrict__ w_hist,    // (3,4)
    const float* __restrict__ b_hist,    // (4)
    const float* __restrict__ wih,       // (30,4)
    const float* __restrict__ whh,       // (30,10)
    const float* __restrict__ bih,       // (30)
    const float* __restrict__ bhh,       // (30)
    const float* __restrict__ w_lane,    // (18,16)
    const float* __restrict__ b_lane,    // (16)
    const float* __restrict__ wf,        // (32,20)
    const float* __restrict__ bf,        // (20)
    const float* __restrict__ wc,        // (4,20)
    const float* __restrict__ bc,        // (20)
    const float* __restrict__ wz,        // (20,20)
    const float* __restrict__ bz,        // (20)
    const float* __restrict__ wo,        // (20,1)
    const float* __restrict__ bo,        // (1)
    const float* __restrict__ emb_const, // (2,4)
    const int*   __restrict__ relation,  // (8,7)
    const int*   __restrict__ pfl,       // (8)
    float* __restrict__ out)             // (B, 8)
{
    // --- GRU weights (col-major) ---
    // wrz_s: 15 cols (x0..3, h0..9, bias) x 24 rows: [r0..r9,pad2,z0..z9,pad2]
    __shared__ __align__(16) float wrz_s[15 * 24];
    __shared__ __align__(16) float win_s[5 * 12];   // cols x0..3,bias; rows n0..9,pad2
    __shared__ __align__(16) float whn_s[11 * 12];  // cols h0..9,bias; rows n0..9,pad2
    __shared__ __align__(16) float wlane_s[18 * 16]; // pre-scaled by 2
    __shared__ __align__(16) float blane_s[16];      // pre-scaled by 2
    // --- pair-stage weights ---
    __shared__ __align__(16) float wf_s[32 * 20];
    __shared__ __align__(16) float wz_s[20 * 20];
    __shared__ __align__(16) float y_s[56 * 20];    // relu(const@wc+bc)
    __shared__ __align__(16) float bf_s[20];
    __shared__ __align__(16) float bz_s[20];
    __shared__ __align__(16) float wo_s[20];
    __shared__ int   pfl_s[8];
    __shared__ float bo_s;
    // --- cross-stage pressures, transposed [feature][thread] ---
    __shared__ float press_s[16][NTHR + 8];

    const int tid = threadIdx.x;

    // wrz_s fill: r rows at 0..9, z rows at 12..21, pads zeroed
    for (int idx = tid; idx < 15 * 24; idx += NTHR) {
        int k = idx / 24, r = idx % 24;
        int j = -1;
        if (r < 10)                 j = r;           // r-gate rows 0..9
        else if (r >= 12 && r < 22) j = r - 12 + 10; // z-gate rows 10..19
        float v = 0.0f;
        if (j >= 0) {
            if (k < 4)        v = wih[j * 4 + k];
            else if (k < 14)  v = whh[j * 10 + (k - 4)];
            else              v = bih[j] + bhh[j];
        }
        wrz_s[idx] = v;
    }
    for (int idx = tid; idx < 5 * 12; idx += NTHR) {
        int k = idx / 12, i = idx % 12;
        float v = 0.0f;
        if (i < 10) v = (k < 4) ? wih[(20 + i) * 4 + k] : bih[20 + i];
        win_s[idx] = v;
    }
    for (int idx = tid; idx < 11 * 12; idx += NTHR) {
        int k = idx / 12, i = idx % 12;
        float v = 0.0f;
        if (i < 10) v = (k < 10) ? whh[(20 + i) * 10 + k] : bhh[20 + i];
        whn_s[idx] = v;
    }
    // pressure = 2*relu(proj) == relu(2*proj): fold the 2x into the weights
    for (int idx = tid; idx < 18 * 16; idx += NTHR) wlane_s[idx] = 2.0f * w_lane[idx];
    if (tid < 16) blane_s[tid] = 2.0f * b_lane[tid];

    for (int idx = tid; idx < 640; idx += NTHR) wf_s[idx] = wf[idx];
    for (int idx = tid; idx < 400; idx += NTHR) wz_s[idx] = wz[idx];
    if (tid < 20) { bf_s[tid] = bf[tid]; bz_s[tid] = bz[tid]; wo_s[tid] = wo[tid]; }
    if (tid < 8) pfl_s[tid] = pfl[tid];
    if (tid == 0) bo_s = bo[0];
    for (int idx = tid; idx < 56 * 20; idx += NTHR) {
        int pr = idx / 20, l = idx % 20;
        int rel = relation[pr];
        float a = bc[l];
        a = fmaf(emb_const[rel * 4 + 0], wc[0 * 20 + l], a);
        a = fmaf(emb_const[rel * 4 + 1], wc[1 * 20 + l], a);
        a = fmaf(emb_const[rel * 4 + 2], wc[2 * 20 + l], a);
        a = fmaf(emb_const[rel * 4 + 3], wc[3 * 20 + l], a);
        y_s[idx] = fmaxf(a, 0.0f);
    }
    __syncthreads();

    const int gid = blockIdx.x * NTHR + tid;
    const int b = gid >> 3;
    const int p = gid & 7;

    // per-thread uniform params (broadcast loads, L1-resident)
    float wh0[4], wh1[4], wh2[4], bh[4];
#pragma unroll
    for (int k = 0; k < 4; k++) {
        wh0[k] = __ldg(&w_hist[k]);
        wh1[k] = __ldg(&w_hist[4 + k]);
        wh2[k] = __ldg(&w_hist[8 + k]);
        bh[k]  = __ldg(&b_hist[k]);
    }

    const int   pbit = (int)feature[b * 16 + p];
    const float veh  = feature[b * 16 + 8 + p];

    float h[10];
#pragma unroll
    for (int i = 0; i < 10; i++) h[i] = 0.0f;

    const float* hp = history + (size_t)b * T_STEPS * 24 + p;
    float c0 = hp[0], c1 = hp[8], c2 = hp[16];

#pragma unroll 1
    for (int t = 0; t < T_STEPS; t++) {
        float n0 = 0.f, n1 = 0.f, n2 = 0.f;
        if (t + 1 < T_STEPS) {
            const float* q = hp + 24;
            n0 = q[0]; n1 = q[8]; n2 = q[16];
            hp = q;
        }

        // x_t = sigmoid(hist3 @ w_hist + b_hist)
        float x[4];
#pragma unroll
        for (int k = 0; k < 4; k++)
            x[k] = sigmoidf(fmaf(c2, wh2[k],
                            fmaf(c1, wh1[k],
                            fmaf(c0, wh0[k], bh[k]))));

        float ng[10];   // n gate result, carried into pass 2
        // ================= pass 1: r, inn, hn -> n =================
        {
            unsigned long long ar[5], ain[5], ahn[5];
            load10(ar,  wrz_s + 14 * 24);       // r-half of bias col
            load10(ain, win_s + 4 * 12);
            load10(ahn, whn_s + 10 * 12);
#pragma unroll
            for (int k = 0; k < 4; k++) {
                unsigned long long vv = pack2(x[k], x[k]);
                fma10(ar,  wrz_s + k * 24, vv);
                fma10(ain, win_s + k * 12, vv);
            }
#pragma unroll
            for (int k = 0; k < 10; k++) {
                unsigned long long vv = pack2(h[k], h[k]);
                fma10(ar,  wrz_s + (4 + k) * 24, vv);
                fma10(ahn, whn_s + k * 12, vv);
            }
#pragma unroll
            for (int m = 0; m < 5; m++) {
                float2 rr = unpack2(ar[m]);
                float2 gi = unpack2(ain[m]);
                float2 gh = unpack2(ahn[m]);
                ng[2 * m]     = tanh_approx(fmaf(sigmoidf(rr.x), gh.x, gi.x));
                ng[2 * m + 1] = tanh_approx(fmaf(sigmoidf(rr.y), gh.y, gi.y));
            }
        }
        // ================= pass 2: z -> h update =================
        {
            unsigned long long az[5];
            load10(az, wrz_s + 14 * 24 + 12);   // z-half of bias col
#pragma unroll
            for (int k = 0; k < 4; k++) {
                unsigned long long vv = pack2(x[k], x[k]);
                fma10(az, wrz_s + k * 24 + 12, vv);
            }
#pragma unroll
            for (int k = 0; k < 10; k++) {
                unsigned long long vv = pack2(h[k], h[k]);
                fma10(az, wrz_s + (4 + k) * 24 + 12, vv);
            }
#pragma unroll
            for (int m = 0; m < 5; m++) {
                float2 zz = unpack2(az[m]);
                float z0 = sigmoidf(zz.x);
                float z1 = sigmoidf(zz.y);
                // h' = n + z*(h - n)
                h[2 * m]     = fmaf(z0, h[2 * m]     - ng[2 * m],     ng[2 * m]);
                h[2 * m + 1] = fmaf(z1, h[2 * m + 1] - ng[2 * m + 1], ng[2 * m + 1]);
            }
        }

        c0 = n0; c1 = n1; c2 = n2;
    }

    // ---- lane projection: relu([f_veh, f_phase, h] @ (2*w_lane) + 2*b_lane) ----
    {
        float lf[18];
#pragma unroll
        for (int k = 0; k < 4; k++) {
            lf[k]     = sigmoidf(fmaf(veh, __ldg(&w_veh[k]), __ldg(&b_veh[k])));
            lf[4 + k] = sigmoidf(__ldg(&emb_phase[pbit * 4 + k]));
        }
#pragma unroll
        for (int i = 0; i < 10; i++) lf[8 + i] = h[i];

        float acc[16];
#pragma unroll
        for (int l = 0; l < 16; l++) acc[l] = blane_s[l];
#pragma unroll
        for (int m = 0; m < 18; m++) {
            float v = lf[m];
            const float4* row = (const float4*)(wlane_s + m * 16);
#pragma unroll
            for (int q = 0; q < 4; q++) {
                float4 w = row[q];
                acc[4 * q + 0] = fmaf(v, w.x, acc[4 * q + 0]);
                acc[4 * q + 1] = fmaf(v, w.y, acc[4 * q + 1]);
                acc[4 * q + 2] = fmaf(v, w.z, acc[4 * q + 2]);
                acc[4 * q + 3] = fmaf(v, w.w, acc[4 * q + 3]);
            }
        }
        // transposed store: conflict-free (lane-consecutive per feature l)
#pragma unroll
        for (int l = 0; l < 16; l++)
            press_s[l][tid] = fmaxf(acc[l], 0.0f);
    }
    __syncthreads();

    // =================== pairwise competition stage ===================
    const int i = p;
    const int rowbase = tid & 0x78;   // this thread's batch-row base in press_s

    float pi[16];
    {
        const int ci = rowbase + pfl_s[i];
#pragma unroll
        for (int l = 0; l < 16; l++) pi[l] = press_s[l][ci];
    }

    float sum = 0.0f;
#pragma unroll 1
    for (int jx = 0; jx < 7; jx++) {
        const int j = jx + (jx >= i ? 1 : 0);
        float pj[16];
        {
            const int cj = rowbase + pfl_s[j];
#pragma unroll
            for (int l = 0; l < 16; l++) pj[l] = press_s[l][cj];
        }

        float xa[20];
        {
            const float4* bfp = (const float4*)bf_s;
#pragma unroll
            for (int q = 0; q < 5; q++) {
                float4 v = bfp[q];
                xa[4 * q + 0] = v.x; xa[4 * q + 1] = v.y;
                xa[4 * q + 2] = v.z; xa[4 * q + 3] = v.w;
            }
        }
#pragma unroll
        for (int m = 0; m < 16; m++) {
            float v = pi[m];
            const float4* row = (const float4*)(wf_s + m * 20);
#pragma unroll
            for (int q = 0; q < 5; q++) {
                float4 w = row[q];
                xa[4 * q + 0] = fmaf(v, w.x, xa[4 * q + 0]);
                xa[4 * q + 1] = fmaf(v, w.y, xa[4 * q + 1]);
                xa[4 * q + 2] = fmaf(v, w.z, xa[4 * q + 2]);
                xa[4 * q + 3] = fmaf(v, w.w, xa[4 * q + 3]);
            }
        }
#pragma unroll
        for (int m = 0; m < 16; m++) {
            float v = pj[m];
            const float4* row = (const float4*)(wf_s + (16 + m) * 20);
#pragma unroll
            for (int q = 0; q < 5; q++) {
                float4 w = row[q];
                xa[4 * q + 0] = fmaf(v, w.x, xa[4 * q + 0]);
                xa[4 * q + 1] = fmaf(v, w.y, xa[4 * q + 1]);
                xa[4 * q + 2] = fmaf(v, w.z, xa[4 * q + 2]);
                xa[4 * q + 3] = fmaf(v, w.w, xa[4 * q + 3]);
            }
        }

        // xa = relu(xa) * y[i][jx]
        const float4* yrow = (const float4*)(y_s + (i * 7 + jx) * 20);
#pragma unroll
        for (int q = 0; q < 5; q++) {
            float4 yv = yrow[q];
            xa[4 * q + 0] = fmaxf(xa[4 * q + 0], 0.0f) * yv.x;
            xa[4 * q + 1] = fmaxf(xa[4 * q + 1], 0.0f) * yv.y;
            xa[4 * q + 2] = fmaxf(xa[4 * q + 2], 0.0f) * yv.z;
            xa[4 * q + 3] = fmaxf(xa[4 * q + 3], 0.0f) * yv.w;
        }

        float z2[20];
        {
            const float4* bzp = (const float4*)bz_s;
#pragma unroll
            for (int q = 0; q < 5; q++) {
                float4 v = bzp[q];
                z2[4 * q + 0] = v.x; z2[4 * q + 1] = v.y;
                z2[4 * q + 2] = v.z; z2[4 * q + 3] = v.w;
            }
        }
#pragma unroll
        for (int m = 0; m < 20; m++) {
            float v = xa[m];
            const float4* row = (const float4*)(wz_s + m * 20);
#pragma unroll
            for (int q = 0; q < 5; q++) {
                float4 w = row[q];
                z2[4 * q + 0] = fmaf(v, w.x, z2[4 * q + 0]);
                z2[4 * q + 1] = fmaf(v, w.y, z2[4 * q + 1]);
                z2[4 * q + 2] = fmaf(v, w.z, z2[4 * q + 2]);
                z2[4 * q + 3] = fmaf(v, w.w, z2[4 * q + 3]);
            }
        }

        float z3 = bo_s;
        const float4* wop = (const float4*)wo_s;
#pragma unroll
        for (int q = 0; q < 5; q++) {
            float4 w = wop[q];
            z3 = fmaf(fmaxf(z2[4 * q + 0], 0.0f), w.x, z3);
            z3 = fmaf(fmaxf(z2[4 * q + 1], 0.0f), w.y, z3);
            z3 = fmaf(fmaxf(z2[4 * q + 2], 0.0f), w.z, z3);
            z3 = fmaf(fmaxf(z2[4 * q + 3], 0.0f), w.w, z3);
        }
        sum += z3;
    }

    out[gid] = sum;
}

extern "C" void kernel_launch(void* const* d_in, const int* in_sizes, int n_in,
                              void* d_out, int out_size) {
    const float* feature   = (const float*)d_in[0];
    const float* history   = (const float*)d_in[1];
    const int*   relation  = (const int*)d_in[2];
    const int*   pfl       = (const int*)d_in[3];
    const float* emb_phase = (const float*)d_in[4];
    const float* w_veh     = (const float*)d_in[5];
    const float* b_veh     = (const float*)d_in[6];
    const float* w_hist    = (const float*)d_in[7];
    const float* b_hist    = (const float*)d_in[8];
    const float* wih       = (const float*)d_in[9];
    const float* whh       = (const float*)d_in[10];
    const float* bih       = (const float*)d_in[11];
    const float* bhh       = (const float*)d_in[12];
    const float* w_lane    = (const float*)d_in[13];
    const float* b_lane    = (const float*)d_in[14];
    const float* emb_const = (const float*)d_in[15];
    const float* wf        = (const float*)d_in[16];
    const float* bfv       = (const float*)d_in[17];
    const float* wc        = (const float*)d_in[18];
    const float* bc        = (const float*)d_in[19];
    const float* wz        = (const float*)d_in[20];
    const float* bz        = (const float*)d_in[21];
    const float* wo        = (const float*)d_in[22];
    const float* bo        = (const float*)d_in[23];

    const int total = B_TOT * P_LANES;            // 65536 threads
    const int blocks = total / NTHR;              // 512 blocks

    frap_kernel<<<blocks, NTHR>>>(feature, history, emb_phase, w_veh, b_veh,
                                  w_hist, b_hist, wih, whh, bih, bhh,
                                  w_lane, b_lane,
                                  wf, bfv, wc, bc, wz, bz, wo, bo,
                                  emb_const, relation, pfl, (float*)d_out);
}